// round 5
// baseline (speedup 1.0000x reference)
#include <cuda_runtime.h>
#include <cuda_bf16.h>

#define BINS 30
#define TPB  128
#define GRID 1036   // 148 SMs * 7 blocks; 7 * 30.7KB = 215KB smem/SM

__device__ float2 g_part[GRID * BINS];
__device__ unsigned int g_ctr = 0;

__device__ __forceinline__ float rcp_approx(float x) {
    float r;
    asm("rcp.approx.f32 %0, %1;" : "=f"(r) : "f"(x));
    return r;
}

// u = x_other - x_true.  g = sigmoid(u) = 1 - 1/(1+e^u),  ce = log(1+e^u).
__device__ __forceinline__ void ghm_elem(float x0, float x1, int t, float2* hrow) {
    float diff = x1 - x0;                                        // FADD
    float u = __int_as_float(__float_as_int(diff) ^ (t << 31));  // SHF + LOP3
    float e = __expf(u);                                         // FMUL + MUFU.EX2
    float s = 1.0f + e;                                          // FADD
    float r = rcp_approx(s);                                     // MUFU.RCP
    float bin_f = fmaf(r, -30.0f, 30.0f);                        // FFMA  (= 30*g)
    bin_f = fminf(bin_f, 29.0f);                                 // FMNMX
    int bin = (int)bin_f;                                        // F2I
    float lg = __log2f(s);                                       // MUFU.LG2

    float2 h = hrow[bin * TPB];                                  // LDS.64
    h.x += 1.0f;                                                 // FADD
    h.y = fmaf(lg, 0.69314718056f, h.y);                         // FFMA (ce = lg*ln2)
    hrow[bin * TPB] = h;                                         // STS.64
}

struct Grp { float4 a, b; int4 t; };

__device__ __forceinline__ Grp load_grp(const float4* __restrict__ x4,
                                        const int4* __restrict__ t4, int g) {
    Grp r;
    r.a = x4[g * 2 + 0];
    r.b = x4[g * 2 + 1];
    r.t = t4[g];
    return r;
}

__device__ __forceinline__ void proc_grp(const Grp& g, float2* hrow) {
    ghm_elem(g.a.x, g.a.y, g.t.x, hrow);
    ghm_elem(g.a.z, g.a.w, g.t.y, hrow);
    ghm_elem(g.b.x, g.b.y, g.t.z, hrow);
    ghm_elem(g.b.z, g.b.w, g.t.w, hrow);
}

__global__ void __launch_bounds__(TPB, 7) ghm_fused(const float4* __restrict__ x4,
                                                    const int4* __restrict__ t4,
                                                    const float2* __restrict__ x2,
                                                    const int* __restrict__ tgt,
                                                    int B,
                                                    float* __restrict__ out,
                                                    int out_size) {
    __shared__ float2 hist[BINS * TPB];   // hist[bin*TPB + tid]: conflict-free
    int tid = threadIdx.x;

    #pragma unroll
    for (int b = 0; b < BINS; b++) hist[b * TPB + tid] = make_float2(0.0f, 0.0f);
    __syncthreads();

    float2* hrow = &hist[tid];

    int gt = blockIdx.x * TPB + tid;
    const int nthreads = GRID * TPB;
    int ngroups = B >> 2;                 // groups of 4 elements

    // depth-2 software pipeline: loads issued two iterations ahead of use.
    int i0 = gt;
    if (i0 < ngroups) {
        Grp s0 = load_grp(x4, t4, i0);
        int i1 = i0 + nthreads;
        if (i1 < ngroups) {
            Grp s1 = load_grp(x4, t4, i1);
            int i2 = i1 + nthreads;
            while (i2 < ngroups) {
                Grp s2 = load_grp(x4, t4, i2);
                proc_grp(s0, hrow);
                s0 = s1; s1 = s2;
                i2 += nthreads;
            }
            proc_grp(s0, hrow);
            proc_grp(s1, hrow);
        } else {
            proc_grp(s0, hrow);
        }
    }
    // scalar tail (B % 4 != 0)
    for (int j = (ngroups << 2) + gt; j < B; j += nthreads) {
        float2 xv = x2[j];
        ghm_elem(xv.x, xv.y, tgt[j], hrow);
    }

    __syncthreads();

    // tree-reduce columns per bin
    for (int s = TPB / 2; s > 0; s >>= 1) {
        if (tid < s) {
            #pragma unroll
            for (int b = 0; b < BINS; b++) {
                float2 p = hist[b * TPB + tid];
                float2 q = hist[b * TPB + tid + s];
                p.x += q.x; p.y += q.y;
                hist[b * TPB + tid] = p;
            }
        }
        __syncthreads();
    }

    // write per-block partials (no atomics, no pre-zero needed)
    if (tid < BINS) g_part[blockIdx.x * BINS + tid] = hist[tid * TPB];
    __threadfence();
    __syncthreads();

    __shared__ bool is_last;
    if (tid == 0) {
        unsigned prev = atomicAdd(&g_ctr, 1u);
        is_last = (prev == GRID - 1);
    }
    __syncthreads();
    if (!is_last) return;

    __threadfence();  // acquire partials written by other blocks

    // re-zero hist, accumulate all partials, tree-reduce
    #pragma unroll
    for (int b = 0; b < BINS; b++) hist[b * TPB + tid] = make_float2(0.0f, 0.0f);
    __syncthreads();

    for (int i = tid; i < GRID * BINS; i += TPB) {
        float2 v = g_part[i];
        int b = i % BINS;
        float2 h = hrow[b * TPB];
        h.x += v.x; h.y += v.y;
        hrow[b * TPB] = h;
    }
    __syncthreads();

    for (int s = TPB / 2; s > 0; s >>= 1) {
        if (tid < s) {
            #pragma unroll
            for (int b = 0; b < BINS; b++) {
                float2 p = hist[b * TPB + tid];
                float2 q = hist[b * TPB + tid + s];
                p.x += q.x; p.y += q.y;
                hist[b * TPB + tid] = p;
            }
        }
        __syncthreads();
    }

    if (tid < 32) {
        float cnt = (tid < BINS) ? hist[tid * TPB].x : 0.0f;
        float ces = (tid < BINS) ? hist[tid * TPB].y : 0.0f;
        float nz   = (cnt > 0.0f) ? 1.0f : 0.0f;
        float term = (cnt > 0.0f) ? ces / (0.25f * cnt) : 0.0f;
        #pragma unroll
        for (int o = 16; o > 0; o >>= 1) {
            nz   += __shfl_xor_sync(0xFFFFFFFFu, nz,   o);
            term += __shfl_xor_sync(0xFFFFFFFFu, term, o);
        }
        if (tid == 0) {
            float loss = term / fmaxf(nz, 1.0f);
            for (int i = 0; i < out_size; i++) out[i] = loss;
            g_ctr = 0;  // reset for next graph replay
        }
    }
}

extern "C" void kernel_launch(void* const* d_in, const int* in_sizes, int n_in,
                              void* d_out, int out_size) {
    const float* x   = (const float*)d_in[0];
    const int*   tgt = (const int*)d_in[1];
    int B = in_sizes[1];   // target element count == batch size

    ghm_fused<<<GRID, TPB>>>((const float4*)x, (const int4*)tgt,
                             (const float2*)x, tgt, B,
                             (float*)d_out, out_size);
}

// round 6
// speedup vs baseline: 1.0064x; 1.0064x over previous
#include <cuda_runtime.h>
#include <cuda_bf16.h>

#define BINS 30
#define TPB  128
#define GRID 592   // 148 SMs * 4 blocks, one wave at 30KB smem/block

__device__ float2 g_part[GRID * BINS];
__device__ unsigned int g_ctr = 0;

// EXACT R1 element math (known-best): max-subtracted softmax form.
__device__ __forceinline__ void ghm_elem(float x0, float x1, int t, float2* hrow) {
    float m  = fmaxf(x0, x1);
    float mn = fminf(x0, x1);
    bool  t1 = (t != 0);
    float xt = t1 ? x1 : x0;
    float xo = t1 ? x0 : x1;
    float e  = __expf(mn - m);          // exp of (smaller - larger)
    float s  = 1.0f + e;
    float et = (xt >= xo) ? 1.0f : e;   // e_true = exp(x_t - m)
    float pt = __fdividef(et, s);
    float g  = fabsf(pt - 1.0f);
    int bin  = (int)(g * 30.0f);
    bin = bin > (BINS - 1) ? (BINS - 1) : bin;
    float ce = (m - xt) + __logf(s);

    float2 h = hrow[bin * TPB];
    h.x += 1.0f;
    h.y += ce;
    hrow[bin * TPB] = h;
}

__global__ void __launch_bounds__(TPB) ghm_fused(const float4* __restrict__ x4,
                                                 const int4* __restrict__ t4,
                                                 const float2* __restrict__ x2,
                                                 const int* __restrict__ tgt,
                                                 int B,
                                                 float* __restrict__ out,
                                                 int out_size) {
    __shared__ float2 hist[BINS * TPB];   // hist[bin*TPB + tid] -> bank-conflict-free
    int tid = threadIdx.x;

    #pragma unroll
    for (int b = 0; b < BINS; b++) hist[b * TPB + tid] = make_float2(0.0f, 0.0f);
    __syncthreads();

    float2* hrow = &hist[tid];

    int gt = blockIdx.x * TPB + tid;
    const int nthreads = GRID * TPB;
    int ngroups = B >> 2;                 // groups of 4 elements

    // EXACT R1 hot loop: plain grid-stride, 4 elements/iter, no prefetch.
    for (int grp = gt; grp < ngroups; grp += nthreads) {
        float4 a = x4[grp * 2];
        float4 b = x4[grp * 2 + 1];
        int4   tt = t4[grp];
        ghm_elem(a.x, a.y, tt.x, hrow);
        ghm_elem(a.z, a.w, tt.y, hrow);
        ghm_elem(b.x, b.y, tt.z, hrow);
        ghm_elem(b.z, b.w, tt.w, hrow);
    }
    // scalar tail (B % 4 != 0)
    for (int j = (ngroups << 2) + gt; j < B; j += nthreads) {
        float2 xv = x2[j];
        ghm_elem(xv.x, xv.y, tgt[j], hrow);
    }

    __syncthreads();

    // tree-reduce columns per bin
    for (int s = TPB / 2; s > 0; s >>= 1) {
        if (tid < s) {
            #pragma unroll
            for (int b = 0; b < BINS; b++) {
                float2 p = hist[b * TPB + tid];
                float2 q = hist[b * TPB + tid + s];
                p.x += q.x; p.y += q.y;
                hist[b * TPB + tid] = p;
            }
        }
        __syncthreads();
    }

    // per-block partials, then last-block finalize (fused: saves 2 launches + zeroing kernel)
    if (tid < BINS) g_part[blockIdx.x * BINS + tid] = hist[tid * TPB];
    __threadfence();
    __syncthreads();

    __shared__ bool is_last;
    if (tid == 0) {
        unsigned prev = atomicAdd(&g_ctr, 1u);
        is_last = (prev == GRID - 1);
    }
    __syncthreads();
    if (!is_last) return;

    __threadfence();  // acquire partials from other blocks

    #pragma unroll
    for (int b = 0; b < BINS; b++) hist[b * TPB + tid] = make_float2(0.0f, 0.0f);
    __syncthreads();

    for (int i = tid; i < GRID * BINS; i += TPB) {
        float2 v = g_part[i];
        int b = i % BINS;
        float2 h = hrow[b * TPB];
        h.x += v.x; h.y += v.y;
        hrow[b * TPB] = h;
    }
    __syncthreads();

    for (int s = TPB / 2; s > 0; s >>= 1) {
        if (tid < s) {
            #pragma unroll
            for (int b = 0; b < BINS; b++) {
                float2 p = hist[b * TPB + tid];
                float2 q = hist[b * TPB + tid + s];
                p.x += q.x; p.y += q.y;
                hist[b * TPB + tid] = p;
            }
        }
        __syncthreads();
    }

    if (tid < 32) {
        float cnt = (tid < BINS) ? hist[tid * TPB].x : 0.0f;
        float ces = (tid < BINS) ? hist[tid * TPB].y : 0.0f;
        float nz   = (cnt > 0.0f) ? 1.0f : 0.0f;
        float term = (cnt > 0.0f) ? ces / (0.25f * cnt) : 0.0f;
        #pragma unroll
        for (int o = 16; o > 0; o >>= 1) {
            nz   += __shfl_xor_sync(0xFFFFFFFFu, nz,   o);
            term += __shfl_xor_sync(0xFFFFFFFFu, term, o);
        }
        if (tid == 0) {
            float loss = term / fmaxf(nz, 1.0f);
            for (int i = 0; i < out_size; i++) out[i] = loss;
            g_ctr = 0;  // reset for next graph replay
        }
    }
}

extern "C" void kernel_launch(void* const* d_in, const int* in_sizes, int n_in,
                              void* d_out, int out_size) {
    const float* x   = (const float*)d_in[0];
    const int*   tgt = (const int*)d_in[1];
    int B = in_sizes[1];   // target element count == batch size

    ghm_fused<<<GRID, TPB>>>((const float4*)x, (const int4*)tgt,
                             (const float2*)x, tgt, B,
                             (float*)d_out, out_size);
}

// round 7
// speedup vs baseline: 1.1231x; 1.1160x over previous
#include <cuda_runtime.h>
#include <cuda_bf16.h>
#include <cstdint>

#define BINS   30
#define TPB    256
#define GRID   296     // 148 SMs * 2 blocks
#define TILE   2048    // elements per tile
#define STAGES 2

// dynamic smem layout (bytes):
//   [0, 61440)              hist: float2[BINS*TPB]
//   [61440, 61440+32768)    xs:   float2[STAGES*TILE]
//   [94208, 94208+16384)    ts:   int[STAGES*TILE]
#define SMEM_HIST 0
#define SMEM_XS   61440
#define SMEM_TS   94208
#define SMEM_TOTAL (SMEM_TS + STAGES * TILE * 4)

__device__ float2 g_part[GRID * BINS];
__device__ unsigned int g_ctr = 0;

__device__ __forceinline__ float rcp_approx(float x) {
    float r;
    asm("rcp.approx.f32 %0, %1;" : "=f"(r) : "f"(x));
    return r;
}

__device__ __forceinline__ void cp_async16(uint32_t saddr, const void* gptr) {
    asm volatile("cp.async.cg.shared.global [%0], [%1], 16;" :: "r"(saddr), "l"(gptr));
}
__device__ __forceinline__ void cp_commit() {
    asm volatile("cp.async.commit_group;");
}
template <int N>
__device__ __forceinline__ void cp_wait() {
    asm volatile("cp.async.wait_group %0;" :: "n"(N));
}

// u = x_other - x_true.  g = sigmoid(u),  ce = log(1+e^u).
__device__ __forceinline__ void ghm_elem(float x0, float x1, int t, float2* hrow) {
    float diff = x1 - x0;
    float u = __int_as_float(__float_as_int(diff) ^ (t << 31));
    float e = __expf(u);
    float s = 1.0f + e;
    float r = rcp_approx(s);
    float bin_f = fmaf(r, -30.0f, 30.0f);     // 30 * (1 - 1/s) = 30*g
    bin_f = fminf(bin_f, 29.0f);
    int bin = (int)bin_f;
    float lg = __log2f(s);

    float2 h = hrow[bin * TPB];
    h.x += 1.0f;
    h.y = fmaf(lg, 0.69314718056f, h.y);      // ce = lg * ln2
    hrow[bin * TPB] = h;
}

// issue cp.asyncs for tile T into stage st (predicated on T < NT); always commits.
__device__ __forceinline__ void issue_tile(const float4* __restrict__ x4,
                                           const int4* __restrict__ t4,
                                           int T, int NT, int st, int tid,
                                           uint32_t xs_s, uint32_t ts_s) {
    if (T < NT) {
        // x: TILE float2 = TILE/2 float4 = 1024 -> 4 per thread
        const float4* xg = x4 + (size_t)T * (TILE / 2);
        uint32_t xd = xs_s + (uint32_t)(st * TILE) * 8u;
        #pragma unroll
        for (int j = 0; j < 4; j++) {
            int i = tid + j * TPB;
            cp_async16(xd + i * 16u, xg + i);
        }
        // t: TILE ints = TILE/4 int4 = 512 -> 2 per thread
        const int4* tg = t4 + (size_t)T * (TILE / 4);
        uint32_t td = ts_s + (uint32_t)(st * TILE) * 4u;
        #pragma unroll
        for (int j = 0; j < 2; j++) {
            int i = tid + j * TPB;
            cp_async16(td + i * 16u, tg + i);
        }
    }
    cp_commit();
}

__global__ void __launch_bounds__(TPB, 2) ghm_fused(const float4* __restrict__ x4,
                                                    const int4* __restrict__ t4,
                                                    const float2* __restrict__ x2,
                                                    const int* __restrict__ tgt,
                                                    int B,
                                                    float* __restrict__ out,
                                                    int out_size) {
    extern __shared__ char smem[];
    float2* hist = (float2*)(smem + SMEM_HIST);
    float2* xs   = (float2*)(smem + SMEM_XS);
    int*    ts   = (int*)(smem + SMEM_TS);
    uint32_t xs_s = (uint32_t)__cvta_generic_to_shared(xs);
    uint32_t ts_s = (uint32_t)__cvta_generic_to_shared(ts);

    int tid = threadIdx.x;
    int bx  = blockIdx.x;

    #pragma unroll
    for (int b = 0; b < BINS; b++) hist[b * TPB + tid] = make_float2(0.0f, 0.0f);
    __syncthreads();

    float2* hrow = &hist[tid];

    int NT = B / TILE;   // full tiles

    // prologue: fill both stages
    issue_tile(x4, t4, bx + 0 * GRID, NT, 0, tid, xs_s, ts_s);
    issue_tile(x4, t4, bx + 1 * GRID, NT, 1, tid, xs_s, ts_s);

    // steady state
    for (int k = 0; ; k++) {
        int T = bx + k * GRID;
        if (T >= NT) break;
        int st = k & 1;

        cp_wait<STAGES - 1>();   // oldest group (this tile) done for this thread
        __syncthreads();         // whole tile visible to all threads

        float2* xst = xs + st * TILE;
        int*    tst = ts + st * TILE;
        #pragma unroll
        for (int j = 0; j < TILE / TPB; j++) {   // 8 elements per thread
            int i = tid + j * TPB;
            float2 xv = xst[i];
            int    tv = tst[i];
            ghm_elem(xv.x, xv.y, tv, hrow);
        }

        __syncthreads();         // stage fully consumed before refill
        issue_tile(x4, t4, bx + (k + STAGES) * GRID, NT, st, tid, xs_s, ts_s);
    }
    cp_wait<0>();

    // tail (B % TILE, zero for this shape): plain global loads
    int gt = bx * TPB + tid;
    for (int j = NT * TILE + gt; j < B; j += GRID * TPB) {
        float2 xv = x2[j];
        ghm_elem(xv.x, xv.y, tgt[j], hrow);
    }

    __syncthreads();

    // tree-reduce columns per bin
    for (int s = TPB / 2; s > 0; s >>= 1) {
        if (tid < s) {
            #pragma unroll
            for (int b = 0; b < BINS; b++) {
                float2 p = hist[b * TPB + tid];
                float2 q = hist[b * TPB + tid + s];
                p.x += q.x; p.y += q.y;
                hist[b * TPB + tid] = p;
            }
        }
        __syncthreads();
    }

    // per-block partials + last-block finalize
    if (tid < BINS) g_part[bx * BINS + tid] = hist[tid * TPB];
    __threadfence();
    __syncthreads();

    __shared__ bool is_last;
    if (tid == 0) {
        unsigned prev = atomicAdd(&g_ctr, 1u);
        is_last = (prev == GRID - 1);
    }
    __syncthreads();
    if (!is_last) return;

    __threadfence();

    #pragma unroll
    for (int b = 0; b < BINS; b++) hist[b * TPB + tid] = make_float2(0.0f, 0.0f);
    __syncthreads();

    for (int i = tid; i < GRID * BINS; i += TPB) {
        float2 v = g_part[i];
        int b = i % BINS;
        float2 h = hrow[b * TPB];
        h.x += v.x; h.y += v.y;
        hrow[b * TPB] = h;
    }
    __syncthreads();

    for (int s = TPB / 2; s > 0; s >>= 1) {
        if (tid < s) {
            #pragma unroll
            for (int b = 0; b < BINS; b++) {
                float2 p = hist[b * TPB + tid];
                float2 q = hist[b * TPB + tid + s];
                p.x += q.x; p.y += q.y;
                hist[b * TPB + tid] = p;
            }
        }
        __syncthreads();
    }

    if (tid < 32) {
        float cnt = (tid < BINS) ? hist[tid * TPB].x : 0.0f;
        float ces = (tid < BINS) ? hist[tid * TPB].y : 0.0f;
        float nz   = (cnt > 0.0f) ? 1.0f : 0.0f;
        float term = (cnt > 0.0f) ? ces / (0.25f * cnt) : 0.0f;
        #pragma unroll
        for (int o = 16; o > 0; o >>= 1) {
            nz   += __shfl_xor_sync(0xFFFFFFFFu, nz,   o);
            term += __shfl_xor_sync(0xFFFFFFFFu, term, o);
        }
        if (tid == 0) {
            float loss = term / fmaxf(nz, 1.0f);
            for (int i = 0; i < out_size; i++) out[i] = loss;
            g_ctr = 0;  // reset for next graph replay
        }
    }
}

extern "C" void kernel_launch(void* const* d_in, const int* in_sizes, int n_in,
                              void* d_out, int out_size) {
    const float* x   = (const float*)d_in[0];
    const int*   tgt = (const int*)d_in[1];
    int B = in_sizes[1];   // target element count == batch size

    cudaFuncSetAttribute(ghm_fused, cudaFuncAttributeMaxDynamicSharedMemorySize, SMEM_TOTAL);
    ghm_fused<<<GRID, TPB, SMEM_TOTAL>>>((const float4*)x, (const int4*)tgt,
                                         (const float2*)x, tgt, B,
                                         (float*)d_out, out_size);
}